// round 1
// baseline (speedup 1.0000x reference)
#include <cuda_runtime.h>

#define D    256
#define N1c  40000
#define N2c  8000
#define E1c  1000000
#define E2c  200000

// ---- scratch (no allocations allowed) ----
__device__ float g_agg1[N1c * D];
__device__ float g_cnt1[N1c];
__device__ float g_inv1[N1c];
__device__ float g_h1[N1c * D];
__device__ float g_agg2[N2c * D];
__device__ float g_cnt2[N2c];
__device__ float g_inv2[N2c];

// ---- zero (float4 grid-stride) ----
__global__ void k_zero4(float4* __restrict__ p, int n4) {
    int i = blockIdx.x * blockDim.x + threadIdx.x;
    int stride = gridDim.x * blockDim.x;
    float4 z = make_float4(0.f, 0.f, 0.f, 0.f);
    for (; i < n4; i += stride) p[i] = z;
}

// ---- edge scatter: one warp per edge, vectorized fp32 reductions ----
__global__ void k_scatter(const float* __restrict__ x,
                          const int* __restrict__ src,
                          const int* __restrict__ dst,
                          float* __restrict__ agg,
                          float* __restrict__ cnt,
                          int ne) {
    int w = (blockIdx.x * blockDim.x + threadIdx.x) >> 5;
    if (w >= ne) return;
    int lane = threadIdx.x & 31;
    int s = __ldg(src + w);
    int d = __ldg(dst + w);
    const float4* xr = reinterpret_cast<const float4*>(x + (size_t)s * D);
    float* ar = agg + (size_t)d * D;
#pragma unroll
    for (int i = 0; i < 2; i++) {
        float4 v = __ldg(xr + lane + 32 * i);
        float* p = ar + (size_t)(lane + 32 * i) * 4;
        asm volatile("red.global.add.v4.f32 [%0], {%1,%2,%3,%4};"
                     :: "l"(p), "f"(v.x), "f"(v.y), "f"(v.z), "f"(v.w)
                     : "memory");
    }
    if (lane == 0) atomicAdd(cnt + d, 1.0f);
}

__global__ void k_inv(const float* __restrict__ cnt, float* __restrict__ inv, int n) {
    int i = blockIdx.x * blockDim.x + threadIdx.x;
    if (i < n) inv[i] = 1.0f / fmaxf(cnt[i], 1.0f);
}

// ---- fused SAGE layer GEMM:
//   out[m, j] = tanh( sum_k mean[m,k]*Wl[j,k] + sum_k xt[m,k]*Wr[j,k] + b[j] )
// as a 128x128x16 tiled SGEMM over logical A = [agg*inv | xt] (M x 512),
// logical B^T = [Wl | Wr] (256 x 512).
__global__ __launch_bounds__(256) void k_sage_gemm(
    const float* __restrict__ agg, const float* __restrict__ inv,
    const float* __restrict__ xt, const float* __restrict__ Wl,
    const float* __restrict__ Wr, const float* __restrict__ bias,
    float* __restrict__ out, int M)
{
    __shared__ __align__(16) float As[16][128];
    __shared__ __align__(16) float Bs[16][128];

    const int m0 = blockIdx.x * 128;
    const int n0 = blockIdx.y * 128;
    const int t  = threadIdx.x;
    const int tm = t >> 1;        // 0..127 : loader row (A) / col (B)
    const int th = t & 1;         // which 8-float half of the 16-wide k slab
    const int gm_l = m0 + tm;
    const bool mval = gm_l < M;
    const float invm = mval ? __ldg(inv + gm_l) : 0.f;
    const float* arow = agg + (size_t)gm_l * D;
    const float* xrow = xt  + (size_t)gm_l * D;
    const int gj_l = n0 + tm;     // output col this thread loads B for (<256 always)

    const int ry = t >> 4;        // 0..15 -> rows ry*8..ry*8+7
    const int rx = t & 15;        // 0..15 -> cols rx*8..rx*8+7

    float acc[8][8];
#pragma unroll
    for (int i = 0; i < 8; i++)
#pragma unroll
        for (int j = 0; j < 8; j++) acc[i][j] = 0.f;

    for (int kt = 0; kt < 32; kt++) {
        const int k0 = kt * 16;
        const bool in_agg = (k0 < 256);
        const int kk0 = in_agg ? k0 : (k0 - 256);

        // --- global loads (A and B slabs) ---
        float4 a0 = make_float4(0.f, 0.f, 0.f, 0.f), a1 = a0;
        if (mval) {
            const float* sp = (in_agg ? arow : xrow) + kk0 + th * 8;
            a0 = *reinterpret_cast<const float4*>(sp);
            a1 = *reinterpret_cast<const float4*>(sp + 4);
            if (in_agg) {
                a0.x *= invm; a0.y *= invm; a0.z *= invm; a0.w *= invm;
                a1.x *= invm; a1.y *= invm; a1.z *= invm; a1.w *= invm;
            }
        }
        const float* W = in_agg ? Wl : Wr;
        const float* bp = W + (size_t)gj_l * D + kk0 + th * 8;
        float4 b0 = *reinterpret_cast<const float4*>(bp);
        float4 b1 = *reinterpret_cast<const float4*>(bp + 4);

        __syncthreads();  // previous iteration's readers done
        {
            const int kb = th * 8;
            As[kb + 0][tm] = a0.x; As[kb + 1][tm] = a0.y;
            As[kb + 2][tm] = a0.z; As[kb + 3][tm] = a0.w;
            As[kb + 4][tm] = a1.x; As[kb + 5][tm] = a1.y;
            As[kb + 6][tm] = a1.z; As[kb + 7][tm] = a1.w;
            Bs[kb + 0][tm] = b0.x; Bs[kb + 1][tm] = b0.y;
            Bs[kb + 2][tm] = b0.z; Bs[kb + 3][tm] = b0.w;
            Bs[kb + 4][tm] = b1.x; Bs[kb + 5][tm] = b1.y;
            Bs[kb + 6][tm] = b1.z; Bs[kb + 7][tm] = b1.w;
        }
        __syncthreads();

#pragma unroll
        for (int kk = 0; kk < 16; kk++) {
            float4 af0 = *reinterpret_cast<const float4*>(&As[kk][ry * 8]);
            float4 af1 = *reinterpret_cast<const float4*>(&As[kk][ry * 8 + 4]);
            float4 bf0 = *reinterpret_cast<const float4*>(&Bs[kk][rx * 8]);
            float4 bf1 = *reinterpret_cast<const float4*>(&Bs[kk][rx * 8 + 4]);
            float a[8] = {af0.x, af0.y, af0.z, af0.w, af1.x, af1.y, af1.z, af1.w};
            float b[8] = {bf0.x, bf0.y, bf0.z, bf0.w, bf1.x, bf1.y, bf1.z, bf1.w};
#pragma unroll
            for (int i = 0; i < 8; i++)
#pragma unroll
                for (int j = 0; j < 8; j++)
                    acc[i][j] = fmaf(a[i], b[j], acc[i][j]);
        }
    }

    // --- epilogue: + bias, tanh, store ---
    float bl[8];
#pragma unroll
    for (int j = 0; j < 8; j++) bl[j] = __ldg(bias + n0 + rx * 8 + j);

#pragma unroll
    for (int i = 0; i < 8; i++) {
        int gm = m0 + ry * 8 + i;
        if (gm < M) {
            float* orow = out + (size_t)gm * D + n0 + rx * 8;
#pragma unroll
            for (int j = 0; j < 8; j++)
                orow[j] = tanhf(acc[i][j] + bl[j]);
        }
    }
}

extern "C" void kernel_launch(void* const* d_in, const int* in_sizes, int n_in,
                              void* d_out, int out_size) {
    const float* nodes = (const float*)d_in[0];
    const float* W_l1  = (const float*)d_in[1];
    const float* b1    = (const float*)d_in[2];
    const float* W_r1  = (const float*)d_in[3];
    const float* W_l2  = (const float*)d_in[4];
    const float* b2    = (const float*)d_in[5];
    const float* W_r2  = (const float*)d_in[6];
    const int*   src1  = (const int*)d_in[7];
    const int*   dst1  = (const int*)d_in[8];
    const int*   src2  = (const int*)d_in[9];
    const int*   dst2  = (const int*)d_in[10];
    float* out = (float*)d_out;

    float *agg1, *cnt1, *inv1, *h1, *agg2, *cnt2, *inv2;
    cudaGetSymbolAddress((void**)&agg1, g_agg1);
    cudaGetSymbolAddress((void**)&cnt1, g_cnt1);
    cudaGetSymbolAddress((void**)&inv1, g_inv1);
    cudaGetSymbolAddress((void**)&h1,   g_h1);
    cudaGetSymbolAddress((void**)&agg2, g_agg2);
    cudaGetSymbolAddress((void**)&cnt2, g_cnt2);
    cudaGetSymbolAddress((void**)&inv2, g_inv2);

    // zero accumulators
    {
        int n4;
        n4 = (N1c * D) / 4; k_zero4<<<(n4 + 255) / 256, 256>>>((float4*)agg1, n4);
        n4 = N1c / 4;       k_zero4<<<(n4 + 255) / 256, 256>>>((float4*)cnt1, n4);
        n4 = (N2c * D) / 4; k_zero4<<<(n4 + 255) / 256, 256>>>((float4*)agg2, n4);
        n4 = N2c / 4;       k_zero4<<<(n4 + 255) / 256, 256>>>((float4*)cnt2, n4);
    }

    // layer 1
    {
        int blocks = (E1c * 32 + 255) / 256;
        k_scatter<<<blocks, 256>>>(nodes, src1, dst1, agg1, cnt1, E1c);
        k_inv<<<(N1c + 255) / 256, 256>>>(cnt1, inv1, N1c);
        dim3 grid((N1c + 127) / 128, 2);
        k_sage_gemm<<<grid, 256>>>(agg1, inv1, nodes, W_l1, W_r1, b1, h1, N1c);
    }

    // layer 2
    {
        int blocks = (E2c * 32 + 255) / 256;
        k_scatter<<<blocks, 256>>>(h1, src2, dst2, agg2, cnt2, E2c);
        k_inv<<<(N2c + 255) / 256, 256>>>(cnt2, inv2, N2c);
        dim3 grid((N2c + 127) / 128, 2);
        k_sage_gemm<<<grid, 256>>>(agg2, inv2, h1, W_l2, W_r2, b2, out, N2c);
    }
}

// round 2
// speedup vs baseline: 1.4061x; 1.4061x over previous
#include <cuda_runtime.h>
#include <cstdint>

#define D    256
#define N1c  40000
#define N2c  8000
#define E1c  1000000
#define E2c  200000

// ---- scratch (no allocations allowed) ----
__device__ float g_agg1[N1c * D];
__device__ float g_cnt1[N1c];
__device__ float g_h1[N1c * D];
__device__ float g_agg2[N2c * D];
__device__ float g_cnt2[N2c];

// ---- zero (float4 grid-stride) ----
__global__ void k_zero4(float4* __restrict__ p, int n4) {
    int i = blockIdx.x * blockDim.x + threadIdx.x;
    int stride = gridDim.x * blockDim.x;
    float4 z = make_float4(0.f, 0.f, 0.f, 0.f);
    for (; i < n4; i += stride) p[i] = z;
}

// ---- edge scatter: one warp per edge, vectorized fp32 reductions ----
__global__ void k_scatter(const float* __restrict__ x,
                          const int* __restrict__ src,
                          const int* __restrict__ dst,
                          float* __restrict__ agg,
                          float* __restrict__ cnt,
                          int ne) {
    int w = (blockIdx.x * blockDim.x + threadIdx.x) >> 5;
    if (w >= ne) return;
    int lane = threadIdx.x & 31;
    int s = __ldg(src + w);
    int d = __ldg(dst + w);
    const float4* xr = reinterpret_cast<const float4*>(x + (size_t)s * D);
    float* ar = agg + (size_t)d * D;
#pragma unroll
    for (int i = 0; i < 2; i++) {
        float4 v = __ldg(xr + lane + 32 * i);
        float* p = ar + (size_t)(lane + 32 * i) * 4;
        asm volatile("red.global.add.v4.f32 [%0], {%1,%2,%3,%4};"
                     :: "l"(p), "f"(v.x), "f"(v.y), "f"(v.z), "f"(v.w)
                     : "memory");
    }
    if (lane == 0) atomicAdd(cnt + d, 1.0f);
}

// ---- tf32 helpers ----
__device__ __forceinline__ uint32_t f2tf(float f) {
    uint32_t u;
    asm("cvt.rna.tf32.f32 %0, %1;" : "=r"(u) : "f"(f));
    return u;
}

__device__ __forceinline__ void mma_tf32(float c[4], const uint32_t a[4], const uint32_t b[2]) {
    asm volatile(
        "mma.sync.aligned.m16n8k8.row.col.f32.tf32.tf32.f32 "
        "{%0,%1,%2,%3}, {%4,%5,%6,%7}, {%8,%9}, {%0,%1,%2,%3};"
        : "+f"(c[0]), "+f"(c[1]), "+f"(c[2]), "+f"(c[3])
        : "r"(a[0]), "r"(a[1]), "r"(a[2]), "r"(a[3]), "r"(b[0]), "r"(b[1]));
}

// ---- fused SAGE layer GEMM on tensor cores (tf32):
//   out[m, j] = tanh( sum_k (agg[m,k]/cnt[m])*Wl[j,k] + sum_k xt[m,k]*Wr[j,k] + b[j] )
// Logical A = [mean | xt] (M x 512), B^T = [Wl | Wr] (256 x 512).
// Block tile 128(M) x 128(N), k-slab 16, 8 warps with 64x32 warp tiles.
__global__ __launch_bounds__(256) void k_sage_mma(
    const float* __restrict__ agg, const float* __restrict__ cnt,
    const float* __restrict__ xt, const float* __restrict__ Wl,
    const float* __restrict__ Wr, const float* __restrict__ bias,
    float* __restrict__ out, int M)
{
    // m/n-major, k in 0..15, stride 20 -> conflict-free fragment LDS
    __shared__ uint32_t As[128][20];
    __shared__ uint32_t Bs[128][20];

    const int m0 = blockIdx.x * 128;
    const int n0 = blockIdx.y * 128;
    const int t  = threadIdx.x;

    // loader mapping: 2 threads per row, each loads an 8-float half of the slab
    const int lrow = t >> 1;
    const int half = t & 1;
    const int gm   = m0 + lrow;
    const bool mval = gm < M;
    const float invm = mval ? 1.0f / fmaxf(__ldg(cnt + gm), 1.0f) : 0.f;
    const float* arow = agg + (size_t)gm * D;
    const float* xrow = xt  + (size_t)gm * D;
    const int gj = n0 + lrow;   // B row (output col), always < 256

    // mma mapping
    const int warp = t >> 5;
    const int lane = t & 31;
    const int gid  = lane >> 2;   // 0..7
    const int tig  = lane & 3;    // 0..3
    const int wm0  = (warp & 1) * 64;
    const int wn0  = (warp >> 1) * 32;

    float acc[4][4][4];
#pragma unroll
    for (int mf = 0; mf < 4; mf++)
#pragma unroll
        for (int nf = 0; nf < 4; nf++)
#pragma unroll
            for (int r = 0; r < 4; r++) acc[mf][nf][r] = 0.f;

    for (int kt = 0; kt < 32; kt++) {
        const int k0 = kt * 16;
        const bool in_agg = (k0 < 256);
        const int kk0 = in_agg ? k0 : (k0 - 256);

        // global loads
        float4 a0 = make_float4(0.f, 0.f, 0.f, 0.f), a1 = a0;
        if (mval) {
            const float* sp = (in_agg ? arow : xrow) + kk0 + half * 8;
            a0 = *reinterpret_cast<const float4*>(sp);
            a1 = *reinterpret_cast<const float4*>(sp + 4);
            if (in_agg) {
                a0.x *= invm; a0.y *= invm; a0.z *= invm; a0.w *= invm;
                a1.x *= invm; a1.y *= invm; a1.z *= invm; a1.w *= invm;
            }
        }
        const float* W  = in_agg ? Wl : Wr;
        const float* bp = W + (size_t)gj * D + kk0 + half * 8;
        float4 b0v = *reinterpret_cast<const float4*>(bp);
        float4 b1v = *reinterpret_cast<const float4*>(bp + 4);

        __syncthreads();   // prev iteration readers done
        {
            const int kb = half * 8;
            As[lrow][kb + 0] = f2tf(a0.x); As[lrow][kb + 1] = f2tf(a0.y);
            As[lrow][kb + 2] = f2tf(a0.z); As[lrow][kb + 3] = f2tf(a0.w);
            As[lrow][kb + 4] = f2tf(a1.x); As[lrow][kb + 5] = f2tf(a1.y);
            As[lrow][kb + 6] = f2tf(a1.z); As[lrow][kb + 7] = f2tf(a1.w);
            Bs[lrow][kb + 0] = f2tf(b0v.x); Bs[lrow][kb + 1] = f2tf(b0v.y);
            Bs[lrow][kb + 2] = f2tf(b0v.z); Bs[lrow][kb + 3] = f2tf(b0v.w);
            Bs[lrow][kb + 4] = f2tf(b1v.x); Bs[lrow][kb + 5] = f2tf(b1v.y);
            Bs[lrow][kb + 6] = f2tf(b1v.z); Bs[lrow][kb + 7] = f2tf(b1v.w);
        }
        __syncthreads();

#pragma unroll
        for (int k8 = 0; k8 < 2; k8++) {
            const int kb2 = k8 * 8;
            uint32_t af[4][4], bf[4][2];
#pragma unroll
            for (int mf = 0; mf < 4; mf++) {
                const int r = wm0 + mf * 16 + gid;
                af[mf][0] = As[r][kb2 + tig];
                af[mf][1] = As[r + 8][kb2 + tig];
                af[mf][2] = As[r][kb2 + tig + 4];
                af[mf][3] = As[r + 8][kb2 + tig + 4];
            }
#pragma unroll
            for (int nf = 0; nf < 4; nf++) {
                const int c = wn0 + nf * 8 + gid;
                bf[nf][0] = Bs[c][kb2 + tig];
                bf[nf][1] = Bs[c][kb2 + tig + 4];
            }
#pragma unroll
            for (int mf = 0; mf < 4; mf++)
#pragma unroll
                for (int nf = 0; nf < 4; nf++)
                    mma_tf32(acc[mf][nf], af[mf], bf[nf]);
        }
    }

    // ---- epilogue: + bias, tanh, store (c0/c1 adjacent cols -> float2) ----
#pragma unroll
    for (int nf = 0; nf < 4; nf++) {
        const int cb = n0 + wn0 + nf * 8 + tig * 2;
        const float bx = __ldg(bias + cb);
        const float by = __ldg(bias + cb + 1);
#pragma unroll
        for (int mf = 0; mf < 4; mf++) {
            const int r0 = m0 + wm0 + mf * 16 + gid;
            if (r0 < M) {
                float2 v;
                v.x = tanhf(acc[mf][nf][0] + bx);
                v.y = tanhf(acc[mf][nf][1] + by);
                *reinterpret_cast<float2*>(out + (size_t)r0 * D + cb) = v;
            }
            const int r1 = r0 + 8;
            if (r1 < M) {
                float2 v;
                v.x = tanhf(acc[mf][nf][2] + bx);
                v.y = tanhf(acc[mf][nf][3] + by);
                *reinterpret_cast<float2*>(out + (size_t)r1 * D + cb) = v;
            }
        }
    }
}

extern "C" void kernel_launch(void* const* d_in, const int* in_sizes, int n_in,
                              void* d_out, int out_size) {
    const float* nodes = (const float*)d_in[0];
    const float* W_l1  = (const float*)d_in[1];
    const float* b1    = (const float*)d_in[2];
    const float* W_r1  = (const float*)d_in[3];
    const float* W_l2  = (const float*)d_in[4];
    const float* b2    = (const float*)d_in[5];
    const float* W_r2  = (const float*)d_in[6];
    const int*   src1  = (const int*)d_in[7];
    const int*   dst1  = (const int*)d_in[8];
    const int*   src2  = (const int*)d_in[9];
    const int*   dst2  = (const int*)d_in[10];
    float* out = (float*)d_out;

    float *agg1, *cnt1, *h1, *agg2, *cnt2;
    cudaGetSymbolAddress((void**)&agg1, g_agg1);
    cudaGetSymbolAddress((void**)&cnt1, g_cnt1);
    cudaGetSymbolAddress((void**)&h1,   g_h1);
    cudaGetSymbolAddress((void**)&agg2, g_agg2);
    cudaGetSymbolAddress((void**)&cnt2, g_cnt2);

    // zero accumulators
    {
        int n4;
        n4 = (N1c * D) / 4; k_zero4<<<(n4 + 255) / 256, 256>>>((float4*)agg1, n4);
        n4 = N1c / 4;       k_zero4<<<(n4 + 255) / 256, 256>>>((float4*)cnt1, n4);
        n4 = (N2c * D) / 4; k_zero4<<<(n4 + 255) / 256, 256>>>((float4*)agg2, n4);
        n4 = N2c / 4;       k_zero4<<<(n4 + 255) / 256, 256>>>((float4*)cnt2, n4);
    }

    // layer 1
    {
        int blocks = (E1c * 32 + 255) / 256;
        k_scatter<<<blocks, 256>>>(nodes, src1, dst1, agg1, cnt1, E1c);
        dim3 grid((N1c + 127) / 128, 2);
        k_sage_mma<<<grid, 256>>>(agg1, cnt1, nodes, W_l1, W_r1, b1, h1, N1c);
    }

    // layer 2
    {
        int blocks = (E2c * 32 + 255) / 256;
        k_scatter<<<blocks, 256>>>(h1, src2, dst2, agg2, cnt2, E2c);
        dim3 grid((N2c + 127) / 128, 2);
        k_sage_mma<<<grid, 256>>>(agg2, cnt2, h1, W_l2, W_r2, b2, out, N2c);
    }
}

// round 3
// speedup vs baseline: 1.6881x; 1.2006x over previous
#include <cuda_runtime.h>
#include <cstdint>

#define D    256
#define N1c  40000
#define N2c  8000
#define E1c  1000000
#define E2c  200000

// ---- scratch (no allocations allowed) ----
__device__ float g_mean1[N1c * D];
__device__ float g_h1[N1c * D];
__device__ float g_mean2[N2c * D];
__device__ int g_cnt1[N1c];
__device__ int g_start1[N1c];
__device__ int g_cur1[N1c];
__device__ int g_cnt2[N2c];
__device__ int g_start2[N2c];
__device__ int g_cur2[N2c];
__device__ int g_ss1[E1c];
__device__ int g_ss2[E2c];

// ---- zero ints ----
__global__ void k_zero_i(int* __restrict__ p, int n) {
    int i = blockIdx.x * blockDim.x + threadIdx.x;
    if (i < n) p[i] = 0;
}

// ---- histogram of dst ----
__global__ void k_hist(const int* __restrict__ dst, int* __restrict__ cnt, int ne) {
    int i = blockIdx.x * blockDim.x + threadIdx.x;
    int stride = gridDim.x * blockDim.x;
    for (; i < ne; i += stride) atomicAdd(&cnt[dst[i]], 1);
}

// ---- single-block exclusive scan (n up to ~64k) ----
__global__ void k_scan(const int* __restrict__ cnt, int* __restrict__ start,
                       int* __restrict__ cursor, int n) {
    __shared__ int sh[32];
    __shared__ int carry;
    const int tid = threadIdx.x;
    if (tid == 0) carry = 0;
    __syncthreads();
    for (int base = 0; base < n; base += 1024) {
        const int i = base + tid;
        const int v = (i < n) ? cnt[i] : 0;
        // warp inclusive scan
        int x = v;
#pragma unroll
        for (int o = 1; o < 32; o <<= 1) {
            int y = __shfl_up_sync(~0u, x, o);
            if ((tid & 31) >= o) x += y;
        }
        if ((tid & 31) == 31) sh[tid >> 5] = x;
        __syncthreads();
        if (tid < 32) {
            int s = sh[tid];
#pragma unroll
            for (int o = 1; o < 32; o <<= 1) {
                int y = __shfl_up_sync(~0u, s, o);
                if (tid >= o) s += y;
            }
            sh[tid] = s;
        }
        __syncthreads();
        const int wpref = (tid >= 32) ? sh[(tid >> 5) - 1] : 0;
        const int incl = x + wpref;
        const int excl = incl - v + carry;
        if (i < n) { start[i] = excl; cursor[i] = excl; }
        __syncthreads();
        if (tid == 0) carry += sh[31];
        __syncthreads();
    }
}

// ---- bucket-scatter src ids into dst-sorted order ----
__global__ void k_sidx(const int* __restrict__ src, const int* __restrict__ dst,
                       int* __restrict__ cursor, int* __restrict__ ss, int ne) {
    int i = blockIdx.x * blockDim.x + threadIdx.x;
    int stride = gridDim.x * blockDim.x;
    for (; i < ne; i += stride) {
        int d = dst[i];
        int p = atomicAdd(&cursor[d], 1);
        ss[p] = src[i];
    }
}

// ---- gather-aggregate: one warp per dst node, register accumulation, writes MEAN ----
__global__ __launch_bounds__(256) void k_gather(
    const float* __restrict__ x, const int* __restrict__ ss,
    const int* __restrict__ start, const int* __restrict__ cnt,
    float* __restrict__ mean, int n)
{
    int w = (blockIdx.x * blockDim.x + threadIdx.x) >> 5;
    if (w >= n) return;
    const int lane = threadIdx.x & 31;
    const int beg = __ldg(start + w);
    const int c = __ldg(cnt + w);
    const int end = beg + c;

    float4 a0 = make_float4(0.f, 0.f, 0.f, 0.f), a1 = a0;
    int i = beg;
    for (; i + 2 <= end; i += 2) {
        const int s0 = __ldg(ss + i);
        const int s1 = __ldg(ss + i + 1);
        const float4* r0 = reinterpret_cast<const float4*>(x + (size_t)s0 * D);
        const float4* r1 = reinterpret_cast<const float4*>(x + (size_t)s1 * D);
        float4 v00 = __ldg(r0 + lane), v01 = __ldg(r0 + lane + 32);
        float4 v10 = __ldg(r1 + lane), v11 = __ldg(r1 + lane + 32);
        a0.x += v00.x + v10.x; a0.y += v00.y + v10.y;
        a0.z += v00.z + v10.z; a0.w += v00.w + v10.w;
        a1.x += v01.x + v11.x; a1.y += v01.y + v11.y;
        a1.z += v01.z + v11.z; a1.w += v01.w + v11.w;
    }
    if (i < end) {
        const int s0 = __ldg(ss + i);
        const float4* r0 = reinterpret_cast<const float4*>(x + (size_t)s0 * D);
        float4 v00 = __ldg(r0 + lane), v01 = __ldg(r0 + lane + 32);
        a0.x += v00.x; a0.y += v00.y; a0.z += v00.z; a0.w += v00.w;
        a1.x += v01.x; a1.y += v01.y; a1.z += v01.z; a1.w += v01.w;
    }
    const float inv = 1.0f / fmaxf((float)c, 1.0f);
    a0.x *= inv; a0.y *= inv; a0.z *= inv; a0.w *= inv;
    a1.x *= inv; a1.y *= inv; a1.z *= inv; a1.w *= inv;
    float4* mr = reinterpret_cast<float4*>(mean + (size_t)w * D);
    mr[lane] = a0;
    mr[lane + 32] = a1;
}

// ---- tf32 helpers ----
__device__ __forceinline__ uint32_t f2tf(float f) {
    uint32_t u;
    asm("cvt.rna.tf32.f32 %0, %1;" : "=r"(u) : "f"(f));
    return u;
}

__device__ __forceinline__ void mma_tf32(float c[4], const uint32_t a[4], const uint32_t b[2]) {
    asm volatile(
        "mma.sync.aligned.m16n8k8.row.col.f32.tf32.tf32.f32 "
        "{%0,%1,%2,%3}, {%4,%5,%6,%7}, {%8,%9}, {%0,%1,%2,%3};"
        : "+f"(c[0]), "+f"(c[1]), "+f"(c[2]), "+f"(c[3])
        : "r"(a[0]), "r"(a[1]), "r"(a[2]), "r"(a[3]), "r"(b[0]), "r"(b[1]));
}

// ---- fused SAGE layer GEMM on tensor cores (tf32):
//   out[m, j] = tanh( sum_k mean[m,k]*Wl[j,k] + sum_k xt[m,k]*Wr[j,k] + b[j] )
__global__ __launch_bounds__(256) void k_sage_mma(
    const float* __restrict__ mean,
    const float* __restrict__ xt, const float* __restrict__ Wl,
    const float* __restrict__ Wr, const float* __restrict__ bias,
    float* __restrict__ out, int M)
{
    __shared__ uint32_t As[128][20];
    __shared__ uint32_t Bs[128][20];

    const int m0 = blockIdx.x * 128;
    const int n0 = blockIdx.y * 128;
    const int t  = threadIdx.x;

    const int lrow = t >> 1;
    const int half = t & 1;
    const int gm   = m0 + lrow;
    const bool mval = gm < M;
    const float* mrow = mean + (size_t)gm * D;
    const float* xrow = xt  + (size_t)gm * D;
    const int gj = n0 + lrow;

    const int warp = t >> 5;
    const int lane = t & 31;
    const int gid  = lane >> 2;
    const int tig  = lane & 3;
    const int wm0  = (warp & 1) * 64;
    const int wn0  = (warp >> 1) * 32;

    float acc[4][4][4];
#pragma unroll
    for (int mf = 0; mf < 4; mf++)
#pragma unroll
        for (int nf = 0; nf < 4; nf++)
#pragma unroll
            for (int r = 0; r < 4; r++) acc[mf][nf][r] = 0.f;

    for (int kt = 0; kt < 32; kt++) {
        const int k0 = kt * 16;
        const bool in_agg = (k0 < 256);
        const int kk0 = in_agg ? k0 : (k0 - 256);

        float4 a0 = make_float4(0.f, 0.f, 0.f, 0.f), a1 = a0;
        if (mval) {
            const float* sp = (in_agg ? mrow : xrow) + kk0 + half * 8;
            a0 = *reinterpret_cast<const float4*>(sp);
            a1 = *reinterpret_cast<const float4*>(sp + 4);
        }
        const float* W  = in_agg ? Wl : Wr;
        const float* bp = W + (size_t)gj * D + kk0 + half * 8;
        float4 b0v = *reinterpret_cast<const float4*>(bp);
        float4 b1v = *reinterpret_cast<const float4*>(bp + 4);

        __syncthreads();
        {
            const int kb = half * 8;
            As[lrow][kb + 0] = f2tf(a0.x); As[lrow][kb + 1] = f2tf(a0.y);
            As[lrow][kb + 2] = f2tf(a0.z); As[lrow][kb + 3] = f2tf(a0.w);
            As[lrow][kb + 4] = f2tf(a1.x); As[lrow][kb + 5] = f2tf(a1.y);
            As[lrow][kb + 6] = f2tf(a1.z); As[lrow][kb + 7] = f2tf(a1.w);
            Bs[lrow][kb + 0] = f2tf(b0v.x); Bs[lrow][kb + 1] = f2tf(b0v.y);
            Bs[lrow][kb + 2] = f2tf(b0v.z); Bs[lrow][kb + 3] = f2tf(b0v.w);
            Bs[lrow][kb + 4] = f2tf(b1v.x); Bs[lrow][kb + 5] = f2tf(b1v.y);
            Bs[lrow][kb + 6] = f2tf(b1v.z); Bs[lrow][kb + 7] = f2tf(b1v.w);
        }
        __syncthreads();

#pragma unroll
        for (int k8 = 0; k8 < 2; k8++) {
            const int kb2 = k8 * 8;
            uint32_t af[4][4], bf[4][2];
#pragma unroll
            for (int mf = 0; mf < 4; mf++) {
                const int r = wm0 + mf * 16 + gid;
                af[mf][0] = As[r][kb2 + tig];
                af[mf][1] = As[r + 8][kb2 + tig];
                af[mf][2] = As[r][kb2 + tig + 4];
                af[mf][3] = As[r + 8][kb2 + tig + 4];
            }
#pragma unroll
            for (int nf = 0; nf < 4; nf++) {
                const int c = wn0 + nf * 8 + gid;
                bf[nf][0] = Bs[c][kb2 + tig];
                bf[nf][1] = Bs[c][kb2 + tig + 4];
            }
#pragma unroll
            for (int mf = 0; mf < 4; mf++)
#pragma unroll
                for (int nf = 0; nf < 4; nf++)
                    mma_tf32(acc[mf][nf], af[mf], bf[nf]);
        }
    }

#pragma unroll
    for (int nf = 0; nf < 4; nf++) {
        const int cb = n0 + wn0 + nf * 8 + tig * 2;
        const float bx = __ldg(bias + cb);
        const float by = __ldg(bias + cb + 1);
#pragma unroll
        for (int mf = 0; mf < 4; mf++) {
            const int r0 = m0 + wm0 + mf * 16 + gid;
            if (r0 < M) {
                float2 v;
                v.x = tanhf(acc[mf][nf][0] + bx);
                v.y = tanhf(acc[mf][nf][1] + by);
                *reinterpret_cast<float2*>(out + (size_t)r0 * D + cb) = v;
            }
            const int r1 = r0 + 8;
            if (r1 < M) {
                float2 v;
                v.x = tanhf(acc[mf][nf][2] + bx);
                v.y = tanhf(acc[mf][nf][3] + by);
                *reinterpret_cast<float2*>(out + (size_t)r1 * D + cb) = v;
            }
        }
    }
}

extern "C" void kernel_launch(void* const* d_in, const int* in_sizes, int n_in,
                              void* d_out, int out_size) {
    const float* nodes = (const float*)d_in[0];
    const float* W_l1  = (const float*)d_in[1];
    const float* b1    = (const float*)d_in[2];
    const float* W_r1  = (const float*)d_in[3];
    const float* W_l2  = (const float*)d_in[4];
    const float* b2    = (const float*)d_in[5];
    const float* W_r2  = (const float*)d_in[6];
    const int*   src1  = (const int*)d_in[7];
    const int*   dst1  = (const int*)d_in[8];
    const int*   src2  = (const int*)d_in[9];
    const int*   dst2  = (const int*)d_in[10];
    float* out = (float*)d_out;

    float *mean1, *h1, *mean2;
    int *cnt1, *start1, *cur1, *cnt2, *start2, *cur2, *ss1, *ss2;
    cudaGetSymbolAddress((void**)&mean1,  g_mean1);
    cudaGetSymbolAddress((void**)&h1,     g_h1);
    cudaGetSymbolAddress((void**)&mean2,  g_mean2);
    cudaGetSymbolAddress((void**)&cnt1,   g_cnt1);
    cudaGetSymbolAddress((void**)&start1, g_start1);
    cudaGetSymbolAddress((void**)&cur1,   g_cur1);
    cudaGetSymbolAddress((void**)&cnt2,   g_cnt2);
    cudaGetSymbolAddress((void**)&start2, g_start2);
    cudaGetSymbolAddress((void**)&cur2,   g_cur2);
    cudaGetSymbolAddress((void**)&ss1,    g_ss1);
    cudaGetSymbolAddress((void**)&ss2,    g_ss2);

    // ---- layer 1 ----
    k_zero_i<<<(N1c + 255) / 256, 256>>>(cnt1, N1c);
    k_hist<<<592, 256>>>(dst1, cnt1, E1c);
    k_scan<<<1, 1024>>>(cnt1, start1, cur1, N1c);
    k_sidx<<<592, 256>>>(src1, dst1, cur1, ss1, E1c);
    k_gather<<<(N1c * 32 + 255) / 256, 256>>>(nodes, ss1, start1, cnt1, mean1, N1c);
    {
        dim3 grid((N1c + 127) / 128, 2);
        k_sage_mma<<<grid, 256>>>(mean1, nodes, W_l1, W_r1, b1, h1, N1c);
    }

    // ---- layer 2 ----
    k_zero_i<<<(N2c + 255) / 256, 256>>>(cnt2, N2c);
    k_hist<<<592, 256>>>(dst2, cnt2, E2c);
    k_scan<<<1, 1024>>>(cnt2, start2, cur2, N2c);
    k_sidx<<<592, 256>>>(src2, dst2, cur2, ss2, E2c);
    k_gather<<<(N2c * 32 + 255) / 256, 256>>>(h1, ss2, start2, cnt2, mean2, N2c);
    {
        dim3 grid((N2c + 127) / 128, 2);
        k_sage_mma<<<grid, 256>>>(mean2, h1, W_l2, W_r2, b2, out, N2c);
    }
}